// round 11
// baseline (speedup 1.0000x reference)
#include <cuda_runtime.h>
#include <stdint.h>

#define NB_COUNT 32
#define DIM 128            // floats per row
#define VEC2 (DIM / 2)     // 64 float2 per row
#define ROW_BYTES 512
#define OFF_NB 8           // neighbors per node staged via cp.async.bulk
#define LDG_NB (NB_COUNT - OFF_NB)   // 24 via LDG.64
#define WARPS 4            // 128-thread blocks

// Hybrid two-pipe gather:
//  - 75% of rows through the L1tex LDG.64 path (proven floor: ~2 cyc/line)
//  - 25% of rows through cp.async.bulk (async proxy, LTS->SMEM, ZERO L1tex
//    wavefronts), overlapped, then summed from SMEM.
// L1 hit rate on this random gather is ~0, so rerouting does not add LTS
// traffic — it only adds a second delivery pipe.
__global__ __launch_bounds__(128, 4) void sum_agg_kernel(
    const int* __restrict__ neighs,
    const float2* __restrict__ emb,   // [num_ids][64] float2
    float2* __restrict__ out,         // [node_count][64] float2
    int node_count)
{
    __shared__ __align__(128) char stage[WARPS][2 * OFF_NB * ROW_BYTES]; // 32KB
    __shared__ __align__(8) unsigned long long mbar[WARPS];

    const int wid  = threadIdx.x >> 5;
    const int lane = threadIdx.x & 31;
    const int warp = blockIdx.x * WARPS + wid;
    const int nodeA = warp * 2;
    const int nodeB = nodeA + 1;

    const unsigned mbar_u32  = (unsigned)__cvta_generic_to_shared(&mbar[wid]);
    const unsigned stage_u32 = (unsigned)__cvta_generic_to_shared(&stage[wid][0]);

    if (lane == 0)
        asm volatile("mbarrier.init.shared.b64 [%0], 1;" :: "r"(mbar_u32) : "memory");
    __syncthreads();

    if (nodeA >= node_count) return;
    const bool hasB = (nodeB < node_count);

    const int idxA = neighs[(size_t)nodeA * NB_COUNT + lane];
    const int idxB = hasB ? neighs[(size_t)nodeB * NB_COUNT + lane] : idxA;

    // ---- Pipe 2: issue 16 bulk copies (rows LDG_NB..31 of both nodes) ----
    if (lane == 0)
        asm volatile("mbarrier.arrive.expect_tx.shared.b64 _, [%0], %1;"
                     :: "r"(mbar_u32), "r"(2 * OFF_NB * ROW_BYTES) : "memory");
    const char* emb_b = (const char*)emb;
    #pragma unroll
    for (int k = 0; k < OFF_NB; ++k) {
        const int rA = __shfl_sync(0xffffffffu, idxA, LDG_NB + k);
        const int rB = __shfl_sync(0xffffffffu, idxB, LDG_NB + k);
        if (lane == 0) {
            asm volatile(
                "cp.async.bulk.shared::cta.global.mbarrier::complete_tx::bytes "
                "[%0], [%1], %2, [%3];"
                :: "r"(stage_u32 + k * ROW_BYTES),
                   "l"(emb_b + (size_t)rA * ROW_BYTES),
                   "r"(ROW_BYTES), "r"(mbar_u32) : "memory");
            asm volatile(
                "cp.async.bulk.shared::cta.global.mbarrier::complete_tx::bytes "
                "[%0], [%1], %2, [%3];"
                :: "r"(stage_u32 + (OFF_NB + k) * ROW_BYTES),
                   "l"(emb_b + (size_t)rB * ROW_BYTES),
                   "r"(ROW_BYTES), "r"(mbar_u32) : "memory");
        }
    }

    // ---- Pipe 1: LDG.64 gather of neighbors 0..23 (overlaps bulk) ----
    float aA0x = 0.f, aA0y = 0.f, aA1x = 0.f, aA1y = 0.f;
    float aB0x = 0.f, aB0y = 0.f, aB1x = 0.f, aB1y = 0.f;

    #pragma unroll
    for (int j = 0; j < LDG_NB; ++j) {
        const int rA = __shfl_sync(0xffffffffu, idxA, j);
        const int rB = __shfl_sync(0xffffffffu, idxB, j);
        const float2* pA = emb + (size_t)rA * VEC2 + lane;
        const float2* pB = emb + (size_t)rB * VEC2 + lane;
        const float2 vA0 = __ldg(pA);
        const float2 vA1 = __ldg(pA + 32);
        const float2 vB0 = __ldg(pB);
        const float2 vB1 = __ldg(pB + 32);
        aA0x += vA0.x; aA0y += vA0.y;
        aA1x += vA1.x; aA1y += vA1.y;
        aB0x += vB0.x; aB0y += vB0.y;
        aB1x += vB1.x; aB1y += vB1.y;
    }

    // ---- Wait for bulk copies, sum staged rows from SMEM ----
    {
        unsigned done;
        asm volatile(
            "{\n\t.reg .pred p;\n\t"
            "mbarrier.try_wait.parity.acquire.cta.shared::cta.b64 p, [%1], 0;\n\t"
            "selp.b32 %0, 1, 0, p;\n\t}"
            : "=r"(done) : "r"(mbar_u32) : "memory");
        while (!done) {
            asm volatile(
                "{\n\t.reg .pred p;\n\t"
                "mbarrier.try_wait.parity.acquire.cta.shared::cta.b64 p, [%1], 0, 0x989680;\n\t"
                "selp.b32 %0, 1, 0, p;\n\t}"
                : "=r"(done) : "r"(mbar_u32) : "memory");
        }
    }

    #pragma unroll
    for (int k = 0; k < OFF_NB; ++k) {
        const float2* sA = (const float2*)(&stage[wid][k * ROW_BYTES]) + lane;
        const float2* sB = (const float2*)(&stage[wid][(OFF_NB + k) * ROW_BYTES]) + lane;
        const float2 vA0 = sA[0],  vA1 = sA[32];
        const float2 vB0 = sB[0],  vB1 = sB[32];
        aA0x += vA0.x; aA0y += vA0.y;
        aA1x += vA1.x; aA1y += vA1.y;
        aB0x += vB0.x; aB0y += vB0.y;
        aB1x += vB1.x; aB1y += vB1.y;
    }

    float2* oA = out + (size_t)nodeA * VEC2 + lane;
    oA[0]  = make_float2(aA0x, aA0y);
    oA[32] = make_float2(aA1x, aA1y);
    if (hasB) {
        float2* oB = out + (size_t)nodeB * VEC2 + lane;
        oB[0]  = make_float2(aB0x, aB0y);
        oB[32] = make_float2(aB1x, aB1y);
    }
}

extern "C" void kernel_launch(void* const* d_in, const int* in_sizes, int n_in,
                              void* d_out, int out_size)
{
    // metadata order: neighs (int32), node_count (int scalar), emb_table (f32)
    const int* neighs = (const int*)d_in[0];
    const float2* emb = (const float2*)d_in[2];
    float2* out = (float2*)d_out;

    const int node_count = out_size / DIM;   // out is [node_count, 128] f32

    const int nodes_per_block = WARPS * 2;   // 8
    const int blocks = (node_count + nodes_per_block - 1) / nodes_per_block;

    sum_agg_kernel<<<blocks, 128>>>(neighs, emb, out, node_count);
}

// round 12
// speedup vs baseline: 1.1413x; 1.1413x over previous
#include <cuda_runtime.h>
#include <stdint.h>

#define NB_COUNT 32
#define DIM 128           // floats per row
#define VEC2 (DIM / 2)    // 64 float2 per row

// FINAL: one warp per node, LDG.64 gathers — the proven optimum of the
// L1tex cost curve for a random 512B-row gather (43.2K line-fetches/SM):
//   LDG.128: (1.0 + 3*2.07)/4 lines = 1.80 cyc/line  -> ~46us (measured R1/R7)
//   LDG.32 : max(1.82 issue, 1.0)   = 1.82 cyc/line  -> ~47us (measured R5)
//   LDG.64 : (1.0 + 2.07)/2 lines   = 1.53 cyc/line  -> ~43.5us (measured R8/R10)
// Saturation verified: occupancy 45->90% and per-warp MLP 2->8x leave dur
// unchanged; L2 eviction hints/pinning neutral; cp.async.bulk hybrid worse
// (bypasses the L1, which absorbs ~half the gather traffic).
// Lane l owns float2 columns l and l+32 of each row.
__global__ __launch_bounds__(256, 8) void sum_agg_kernel(
    const int* __restrict__ neighs,
    const float2* __restrict__ emb,   // [num_ids][64] float2
    float2* __restrict__ out,         // [node_count][64] float2
    int node_count)
{
    const int warp = (blockIdx.x * blockDim.x + threadIdx.x) >> 5;
    const int lane = threadIdx.x & 31;
    if (warp >= node_count) return;

    // Coalesced index load: lane l gets neighbor l of this node.
    const int my_idx = neighs[(size_t)warp * NB_COUNT + lane];

    float ax0 = 0.f, ay0 = 0.f;   // column l
    float ax1 = 0.f, ay1 = 0.f;   // column l+32

    #pragma unroll
    for (int j = 0; j < NB_COUNT; ++j) {
        const int r = __shfl_sync(0xffffffffu, my_idx, j);
        const float2* row = emb + (size_t)r * VEC2 + lane;
        const float2 v0 = __ldg(row);        // LDG.64, lines 0-1 of the row
        const float2 v1 = __ldg(row + 32);   // LDG.64, lines 2-3 of the row
        ax0 += v0.x; ay0 += v0.y;
        ax1 += v1.x; ay1 += v1.y;
    }

    float2* o = out + (size_t)warp * VEC2 + lane;
    o[0]  = make_float2(ax0, ay0);
    o[32] = make_float2(ax1, ay1);
}

extern "C" void kernel_launch(void* const* d_in, const int* in_sizes, int n_in,
                              void* d_out, int out_size)
{
    // metadata order: neighs (int32), node_count (int scalar), emb_table (f32)
    const int* neighs = (const int*)d_in[0];
    const float2* emb = (const float2*)d_in[2];
    float2* out = (float2*)d_out;

    const int node_count = out_size / DIM;   // out is [node_count, 128] f32

    const int threads = 256;                  // 8 warps = 8 nodes per block
    const int blocks = (node_count * 32 + threads - 1) / threads;

    sum_agg_kernel<<<blocks, threads>>>(neighs, emb, out, node_count);
}